// round 12
// baseline (speedup 1.0000x reference)
#include <cuda_runtime.h>
#include <cstdint>
#include <math.h>

#define TT 4096
#define DD 4096
#define VV 32000
#define NCHUNK 4                       // D split into 4 chunks of 1024 floats
#define ROWS_PB 16                     // rows per pre-block
#define PRE_BLOCKS ((TT / ROWS_PB) * 4)        // 1024
#define MOM_BLOCKS (11 * 4)            // j x v-chunk

// k3 geometry: 256 row-tiles x 10 v-chunks; sub-tile = 16 rows x 320 cols
#define K3_THREADS 320
#define K3_VCHUNK 3200
#define K3_SUBCOLS 320
#define K3_NSUB (K3_VCHUNK / K3_SUBCOLS)   // 10
#define K3_BLOCKS (256 * (VV / K3_VCHUNK)) // 2560

// ---------------- scratch (device globals; no allocations) ----------------
__device__ float g_part[NCHUNK * TT * 2];   // partial pre sums, [chunk][t][h]
__device__ float g_h0[TT];
__device__ float g_h1[TT];
__device__ float g_Cm[4 * 121];             // moment partials per v-chunk

__device__ __constant__ float c_invfact[11] = {
    1.0f, 1.0f, 0.5f, 1.6666667e-1f, 4.1666668e-2f, 8.3333338e-3f,
    1.3888889e-3f, 1.9841270e-4f, 2.4801588e-5f, 2.7557319e-6f, 2.7557319e-7f
};

__device__ __forceinline__ unsigned int smem_u32(const void* p) {
    unsigned int a;
    asm("{ .reg .u64 t; cvta.to.shared.u64 t, %1; cvt.u32.u64 %0, t; }"
        : "=r"(a) : "l"(p));
    return a;
}

// accurate-enough tanh: exact +-1 in saturation (matches fp32 tanh rounding),
// ~1e-7 error elsewhere (EX2 + RCP)
__device__ __forceinline__ float tanh_acc(float a) {
    float ab = fabsf(a);
    if (ab > 9.1f) return copysignf(1.0f, a);
    float e = __expf(-2.0f * ab);
    float r = __fdividef(1.0f - e, 1.0f + e);
    return copysignf(r, a);
}

// ---------------- K1: pre-GEMV partials (16 rows/thread-col, butterfly red) --
__global__ __launch_bounds__(256, 2) void k1_pre_moments(const float* __restrict__ x,
                                                         const float* __restrict__ Wih,
                                                         const float* __restrict__ Wfc,
                                                         const float* __restrict__ bfc) {
    int b = blockIdx.x;
    int tid = threadIdx.x;

    if (b < PRE_BLOCKS) {
        int rt = b >> 2;                 // row tile (0..255)
        int c  = b & 3;                  // D-chunk (0..3)
        int t0 = rt * ROWS_PB;
        int i  = c * 256 + tid;          // float4 column index within row

        const float4* w0g = (const float4*)(Wih);
        const float4* w1g = (const float4*)(Wih + DD);
        float4 w0 = __ldg(&w0g[i]);
        float4 w1 = __ldg(&w1g[i]);

        // 16 independent streaming loads, front-batched for MLP
        float4 xv[ROWS_PB];
        const float4* xb = (const float4*)(x) + (size_t)t0 * (DD / 4) + i;
#pragma unroll
        for (int r = 0; r < ROWS_PB; r++) xv[r] = __ldcs(xb + (size_t)r * (DD / 4));

        float a[32];
#pragma unroll
        for (int r = 0; r < ROWS_PB; r++) {
            float4 v = xv[r];
            a[2 * r]     = fmaf(v.x, w0.x, fmaf(v.y, w0.y, fmaf(v.z, w0.z, v.w * w0.w)));
            a[2 * r + 1] = fmaf(v.x, w1.x, fmaf(v.y, w1.y, fmaf(v.z, w1.z, v.w * w1.w)));
        }

        // butterfly multi-value reduce: 31 shfls; lane l ends holding slot l
        int lane = tid & 31;
#pragma unroll
        for (int o = 16; o; o >>= 1) {
#pragma unroll
            for (int j = 0; j < o; j++) {
                bool hi = (lane & o);
                float pass = hi ? a[j] : a[j + o];
                float recv = __shfl_xor_sync(0xffffffffu, pass, o);
                a[j] = (hi ? a[j + o] : a[j]) + recv;
            }
        }

        __shared__ float sred[8][33];
        int wid = tid >> 5;
        sred[wid][lane] = a[0];
        __syncthreads();
        if (tid < 32) {
            float s = 0.f;
#pragma unroll
            for (int w = 0; w < 8; w++) s += sred[w][tid];
            g_part[((size_t)c * TT + t0) * 2 + tid] = s;
        }
    } else {
        // ---- moments partials: block (j, vc), each covers V/4 elements ----
        int m = b - PRE_BLOCKS;
        int j  = m >> 2;
        int vc = m & 3;
        float acc[11];
#pragma unroll
        for (int k = 0; k < 11; k++) acc[k] = 0.f;

        int vbeg = vc * (VV / 4), vend = vbeg + (VV / 4);
        for (int v = vbeg + tid; v < vend; v += 256) {
            float2 w = *(const float2*)(Wfc + 2 * v);
            float p = __expf(bfc[v]);
#pragma unroll
            for (int a2 = 0; a2 < 10; a2++) {
                if (a2 < j) p *= w.x;
            }
#pragma unroll
            for (int k = 0; k < 11; k++) {
                acc[k] += p;
                p *= w.y;
            }
        }
        __shared__ float sredm[8][11];
#pragma unroll
        for (int k = 0; k < 11; k++) {
#pragma unroll
            for (int o = 16; o; o >>= 1)
                acc[k] += __shfl_down_sync(0xffffffffu, acc[k], o);
        }
        if ((tid & 31) == 0) {
#pragma unroll
            for (int k = 0; k < 11; k++) sredm[tid >> 5][k] = acc[k];
        }
        __syncthreads();
        if (tid < 11) {
            float tot = 0.f;
#pragma unroll
            for (int w = 0; w < 8; w++) tot += sredm[w][tid];
            g_Cm[vc * 121 + j * 11 + tid] = tot * c_invfact[j] * c_invfact[tid];
        }
    }
}

// ---------------- K2: sum partials + biases (front-batched), segmented scan --
__global__ __launch_bounds__(1024) void k2_scan(const float* __restrict__ Whh,
                                                const float* __restrict__ bih,
                                                const float* __restrict__ bhh) {
    __shared__ float sp0[TT];
    __shared__ float sp1[TT];
    int tid = threadIdx.x;
    float c0 = bih[0] + bhh[0];
    float c1 = bih[1] + bhh[1];
    for (int t = tid; t < TT; t += 1024) {
        float2 v[NCHUNK];
#pragma unroll
        for (int c = 0; c < NCHUNK; c++)
            v[c] = *(const float2*)&g_part[((size_t)c * TT + t) * 2];
        float p0 = c0, p1 = c1;
#pragma unroll
        for (int c = 0; c < NCHUNK; c++) { p0 += v[c].x; p1 += v[c].y; }
        sp0[t] = p0;
        sp1[t] = p1;
    }
    __syncthreads();

    float W00 = Whh[0], W01 = Whh[1], W10 = Whh[2], W11 = Whh[3];
    float th0 = 9.2f + fabsf(W00) + fabsf(W01);
    float th1 = 9.2f + fabsf(W10) + fabsf(W11);

#pragma unroll
    for (int k = 0; k < 5; k++) {
        int idx = tid + k * 1024;
        if (k == 4 && tid != 0) break;
        if (k == 4) idx = TT;

        float h0, h1;
        int t;
        if (idx == 0) {
            h0 = 0.f; h1 = 0.f; t = 0;
        } else {
            int r = idx - 1;
            float p0 = sp0[r], p1 = sp1[r];
            if (!(fabsf(p0) > th0 && fabsf(p1) > th1)) continue;
            h0 = copysignf(1.0f, p0);   // saturated: tanh == +-1.0f exactly
            h1 = copysignf(1.0f, p1);
            g_h0[r] = h0;
            g_h1[r] = h1;
            t = r + 1;
        }
        while (t < TT) {
            float p0 = sp0[t], p1 = sp1[t];
            if (fabsf(p0) > th0 && fabsf(p1) > th1) break;
            float a0 = fmaf(W01, h1, fmaf(W00, h0, p0));
            float a1 = fmaf(W11, h1, fmaf(W10, h0, p1));
            h0 = tanh_acc(a0);
            h1 = tanh_acc(a1);
            g_h0[t] = h0;
            g_h1[t] = h1;
            t++;
        }
    }
}

// ---------------- K3: logits via SMEM + cp.async.bulk stores, loss fused -----
// blockIdx 0 = loss; blocks 1..K3_BLOCKS = logits.
// logits block bb2: row-tile rt = bb2 & 255 (16 rows), v-chunk = bb2 >> 8 (3200 cols)
// thread = rh*80 + cg: rh in 0..3 (4 rows each), cg in 0..79 (4 cols each)
__global__ __launch_bounds__(K3_THREADS) void k3_logits_loss(const float* __restrict__ Wfc,
                                                             const float* __restrict__ bfc,
                                                             const int* __restrict__ tgt_raw,
                                                             float* __restrict__ out,
                                                             long long loss_idx,
                                                             int n_logit_blocks) {
    int b = blockIdx.x;
    int tid = threadIdx.x;

    if (b > 0 && b <= n_logit_blocks) {
        // ------------- logits -------------
        __shared__ float4 sbuf[2][16 * 80];     // 2 x 16 rows x 320 cols = 40960B
        __shared__ float sh0[16], sh1[16];
        int bb2 = b - 1;
        int tb = (bb2 & 255) * 16;
        int vbeg = (bb2 >> 8) * K3_VCHUNK;
        if (tid < 16) {
            sh0[tid] = g_h0[tb + tid];
            sh1[tid] = g_h1[tb + tid];
        }
        __syncthreads();

        int rh = tid / 80;                       // 0..3
        int cg = tid - rh * 80;                  // 0..79
        float h0r[4], h1r[4];
#pragma unroll
        for (int j = 0; j < 4; j++) {
            h0r[j] = sh0[rh * 4 + j];
            h1r[j] = sh1[rh * 4 + j];
        }

        unsigned int sb0 = smem_u32(&sbuf[0][0]);

#pragma unroll 1
        for (int sub = 0; sub < K3_NSUB; sub++) {
            int buf = sub & 1;
            if (sub >= 2) {
                if (tid == 0)
                    asm volatile("cp.async.bulk.wait_group.read 1;" ::: "memory");
                __syncthreads();                 // buffer 'buf' is free again
            }
            int v = vbeg + sub * K3_SUBCOLS + cg * 4;
            float4 wa = *(const float4*)(Wfc + 2 * v);      // w0,w1 of v, v+1
            float4 wb = *(const float4*)(Wfc + 2 * v + 4);  // w0,w1 of v+2, v+3
            float4 bb = *(const float4*)(bfc + v);
#pragma unroll
            for (int j = 0; j < 4; j++) {
                float4 o;
                o.x = fmaf(h0r[j], wa.x, fmaf(h1r[j], wa.y, bb.x));
                o.y = fmaf(h0r[j], wa.z, fmaf(h1r[j], wa.w, bb.y));
                o.z = fmaf(h0r[j], wb.x, fmaf(h1r[j], wb.y, bb.z));
                o.w = fmaf(h0r[j], wb.z, fmaf(h1r[j], wb.w, bb.w));
                sbuf[buf][(rh * 4 + j) * 80 + cg] = o;
            }
            __syncthreads();                     // tile complete in smem
            if (tid == 0) {
                asm volatile("fence.proxy.async;" ::: "memory");
#pragma unroll
                for (int r = 0; r < 16; r++) {
                    const float* gp = out + (size_t)(tb + r) * VV + vbeg + sub * K3_SUBCOLS;
                    unsigned int sp = sb0 + (unsigned int)(buf * 16 + r) * (80 * 16);
                    asm volatile(
                        "cp.async.bulk.global.shared::cta.bulk_group [%0], [%1], %2;"
                        :: "l"(gp), "r"(sp), "r"(K3_SUBCOLS * 4) : "memory");
                }
                asm volatile("cp.async.bulk.commit_group;" ::: "memory");
            }
        }
        if (tid == 0)
            asm volatile("cp.async.bulk.wait_group 0;" ::: "memory");
    } else if (b == 0) {
        // ------------- loss (wave-1 block, hides under logits stores) ---------
        __shared__ float sC[121];
        if (tid < 121)
            sC[tid] = g_Cm[tid] + g_Cm[121 + tid] + g_Cm[242 + tid] + g_Cm[363 + tid];

        // detect int64 vs int32 targets: int64 (LE) => all odd 32-bit words of
        // the first 4096 words are zero (values < 32000). OOB-safe either way.
        int local = 0;
        for (int i = tid; i < TT / 2; i += K3_THREADS) local |= tgt_raw[2 * i + 1];
        int nz = __syncthreads_or(local);
        int is64 = (nz == 0);

        float acc = 0.f;
        for (int t = tid; t < TT; t += K3_THREADS) {
            float h0 = g_h0[t];
            float h1 = g_h1[t];
            // sumexp(h) = sum_{j,k<=10} C_jk h0^j h1^k (double Horner)
            float S = 0.f;
#pragma unroll
            for (int j = 10; j >= 0; j--) {
                const float* row = &sC[j * 11];
                float inner = row[10];
#pragma unroll
                for (int k = 9; k >= 0; k--) inner = fmaf(inner, h1, row[k]);
                S = fmaf(S, h0, inner);
            }
            int g = is64 ? tgt_raw[2 * t] : tgt_raw[t];
            float lt = fmaf(h0, Wfc[2 * g], fmaf(h1, Wfc[2 * g + 1], bfc[g]));
            acc += logf(S) - lt;
        }

#pragma unroll
        for (int o = 16; o; o >>= 1) acc += __shfl_down_sync(0xffffffffu, acc, o);
        __shared__ float s[10];
        if ((tid & 31) == 0) s[tid >> 5] = acc;
        __syncthreads();
        if (tid == 0) {
            float tot = 0.f;
#pragma unroll
            for (int w = 0; w < 10; w++) tot += s[w];
            if (loss_idx >= 0) out[loss_idx] = tot * (1.0f / TT);
        }
    }
}

// ---------------- launch ----------------
extern "C" void kernel_launch(void* const* d_in, const int* in_sizes, int n_in,
                              void* d_out, int out_size) {
    const float* x       = (const float*)d_in[0];
    const int*   targets = (const int*)d_in[1];   // int32 or int64, detected on device
    const float* Wih     = (const float*)d_in[2];
    const float* bih     = (const float*)d_in[3];
    const float* Whh     = (const float*)d_in[4];
    const float* bhh     = (const float*)d_in[5];
    const float* Wfc     = (const float*)d_in[6];
    const float* bfc     = (const float*)d_in[7];
    float* out = (float*)d_out;

    const long long logits_elems = (long long)TT * VV;

    k1_pre_moments<<<PRE_BLOCKS + MOM_BLOCKS, 256>>>(x, Wih, Wfc, bfc);
    k2_scan<<<1, 1024>>>(Whh, bih, bhh);

    int n_logit_blocks = ((long long)out_size >= logits_elems) ? K3_BLOCKS : 0;
    long long loss_idx = -1;
    if ((long long)out_size > logits_elems) loss_idx = logits_elems;  // logits + loss
    else if (out_size == 1) loss_idx = 0;                             // loss only
    k3_logits_loss<<<n_logit_blocks + 1, K3_THREADS>>>(Wfc, bfc, targets, out,
                                                       loss_idx, n_logit_blocks);
}

// round 13
// speedup vs baseline: 2.1304x; 2.1304x over previous
#include <cuda_runtime.h>
#include <math.h>

#define TT 4096
#define DD 4096
#define VV 32000
#define NCHUNK 4                       // D split into 4 chunks of 1024 floats
#define ROWS_PB 16                     // rows per pre-block
#define PRE_BLOCKS ((TT / ROWS_PB) * 4)        // 1024
#define MOM_BLOCKS (11 * 4)            // j x v-chunk

// ---------------- scratch (device globals; no allocations) ----------------
__device__ float g_part[NCHUNK * TT * 2];   // partial pre sums, [chunk][t][h]
__device__ float g_h0[TT];
__device__ float g_h1[TT];
__device__ float g_Cm[4 * 121];             // moment partials per v-chunk

__device__ __constant__ float c_invfact[11] = {
    1.0f, 1.0f, 0.5f, 1.6666667e-1f, 4.1666668e-2f, 8.3333338e-3f,
    1.3888889e-3f, 1.9841270e-4f, 2.4801588e-5f, 2.7557319e-6f, 2.7557319e-7f
};

// accurate-enough tanh: exact +-1 in saturation (matches fp32 tanh rounding),
// ~1e-7 error elsewhere (EX2 + RCP)
__device__ __forceinline__ float tanh_acc(float a) {
    float ab = fabsf(a);
    if (ab > 9.1f) return copysignf(1.0f, a);
    float e = __expf(-2.0f * ab);
    float r = __fdividef(1.0f - e, 1.0f + e);
    return copysignf(r, a);
}

// ---------------- K1: pre-GEMV partials (16 rows/thread-col, butterfly red) --
__global__ __launch_bounds__(256, 2) void k1_pre_moments(const float* __restrict__ x,
                                                         const float* __restrict__ Wih,
                                                         const float* __restrict__ Wfc,
                                                         const float* __restrict__ bfc) {
    int b = blockIdx.x;
    int tid = threadIdx.x;

    if (b < PRE_BLOCKS) {
        int rt = b >> 2;                 // row tile (0..255)
        int c  = b & 3;                  // D-chunk (0..3)
        int t0 = rt * ROWS_PB;
        int i  = c * 256 + tid;          // float4 column index within row

        const float4* w0g = (const float4*)(Wih);
        const float4* w1g = (const float4*)(Wih + DD);
        float4 w0 = __ldg(&w0g[i]);
        float4 w1 = __ldg(&w1g[i]);

        // 16 independent streaming loads, front-batched for MLP
        float4 xv[ROWS_PB];
        const float4* xb = (const float4*)(x) + (size_t)t0 * (DD / 4) + i;
#pragma unroll
        for (int r = 0; r < ROWS_PB; r++) xv[r] = __ldcs(xb + (size_t)r * (DD / 4));

        float a[32];
#pragma unroll
        for (int r = 0; r < ROWS_PB; r++) {
            float4 v = xv[r];
            a[2 * r]     = fmaf(v.x, w0.x, fmaf(v.y, w0.y, fmaf(v.z, w0.z, v.w * w0.w)));
            a[2 * r + 1] = fmaf(v.x, w1.x, fmaf(v.y, w1.y, fmaf(v.z, w1.z, v.w * w1.w)));
        }

        // butterfly multi-value reduce: 31 shfls; lane l ends holding slot l
        int lane = tid & 31;
#pragma unroll
        for (int o = 16; o; o >>= 1) {
#pragma unroll
            for (int j = 0; j < o; j++) {
                bool hi = (lane & o);
                float pass = hi ? a[j] : a[j + o];
                float recv = __shfl_xor_sync(0xffffffffu, pass, o);
                a[j] = (hi ? a[j + o] : a[j]) + recv;
            }
        }

        __shared__ float sred[8][33];
        int wid = tid >> 5;
        sred[wid][lane] = a[0];
        __syncthreads();
        if (tid < 32) {
            float s = 0.f;
#pragma unroll
            for (int w = 0; w < 8; w++) s += sred[w][tid];
            g_part[((size_t)c * TT + t0) * 2 + tid] = s;
        }
    } else {
        // ---- moments partials: block (j, vc), each covers V/4 elements ----
        int m = b - PRE_BLOCKS;
        int j  = m >> 2;
        int vc = m & 3;
        float acc[11];
#pragma unroll
        for (int k = 0; k < 11; k++) acc[k] = 0.f;

        int vbeg = vc * (VV / 4), vend = vbeg + (VV / 4);
        for (int v = vbeg + tid; v < vend; v += 256) {
            float2 w = *(const float2*)(Wfc + 2 * v);
            float p = __expf(bfc[v]);
#pragma unroll
            for (int a2 = 0; a2 < 10; a2++) {
                if (a2 < j) p *= w.x;
            }
#pragma unroll
            for (int k = 0; k < 11; k++) {
                acc[k] += p;
                p *= w.y;
            }
        }
        __shared__ float sredm[8][11];
#pragma unroll
        for (int k = 0; k < 11; k++) {
#pragma unroll
            for (int o = 16; o; o >>= 1)
                acc[k] += __shfl_down_sync(0xffffffffu, acc[k], o);
        }
        if ((tid & 31) == 0) {
#pragma unroll
            for (int k = 0; k < 11; k++) sredm[tid >> 5][k] = acc[k];
        }
        __syncthreads();
        if (tid < 11) {
            float tot = 0.f;
#pragma unroll
            for (int w = 0; w < 8; w++) tot += sredm[w][tid];
            g_Cm[vc * 121 + j * 11 + tid] = tot * c_invfact[j] * c_invfact[tid];
        }
    }
}

// ---------------- K2: sum partials + biases (front-batched), segmented scan --
__global__ __launch_bounds__(1024) void k2_scan(const float* __restrict__ Whh,
                                                const float* __restrict__ bih,
                                                const float* __restrict__ bhh) {
    __shared__ float sp0[TT];
    __shared__ float sp1[TT];
    int tid = threadIdx.x;
    float c0 = bih[0] + bhh[0];
    float c1 = bih[1] + bhh[1];
    for (int t = tid; t < TT; t += 1024) {
        float2 v[NCHUNK];
#pragma unroll
        for (int c = 0; c < NCHUNK; c++)
            v[c] = *(const float2*)&g_part[((size_t)c * TT + t) * 2];
        float p0 = c0, p1 = c1;
#pragma unroll
        for (int c = 0; c < NCHUNK; c++) { p0 += v[c].x; p1 += v[c].y; }
        sp0[t] = p0;
        sp1[t] = p1;
    }
    __syncthreads();

    float W00 = Whh[0], W01 = Whh[1], W10 = Whh[2], W11 = Whh[3];
    float th0 = 9.2f + fabsf(W00) + fabsf(W01);
    float th1 = 9.2f + fabsf(W10) + fabsf(W11);

#pragma unroll
    for (int k = 0; k < 5; k++) {
        int idx = tid + k * 1024;
        if (k == 4 && tid != 0) break;
        if (k == 4) idx = TT;

        float h0, h1;
        int t;
        if (idx == 0) {
            h0 = 0.f; h1 = 0.f; t = 0;
        } else {
            int r = idx - 1;
            float p0 = sp0[r], p1 = sp1[r];
            if (!(fabsf(p0) > th0 && fabsf(p1) > th1)) continue;
            h0 = copysignf(1.0f, p0);   // saturated: tanh == +-1.0f exactly
            h1 = copysignf(1.0f, p1);
            g_h0[r] = h0;
            g_h1[r] = h1;
            t = r + 1;
        }
        while (t < TT) {
            float p0 = sp0[t], p1 = sp1[t];
            if (fabsf(p0) > th0 && fabsf(p1) > th1) break;
            float a0 = fmaf(W01, h1, fmaf(W00, h0, p0));
            float a1 = fmaf(W11, h1, fmaf(W10, h0, p1));
            h0 = tanh_acc(a0);
            h1 = tanh_acc(a1);
            g_h0[t] = h0;
            g_h1[t] = h1;
            t++;
        }
    }
}

// ---------------- K3: logits (HBM-write bound, 8-row tiles for occupancy) ----
// loss block = blockIdx 0; logits blocks = 1..n_logit_blocks
// logits block bb2: t-tile = (bb2 & 511)*8, v-chunk = (bb2 >> 9)*4000
__global__ __launch_bounds__(256) void k3_logits_loss(const float* __restrict__ Wfc,
                                                      const float* __restrict__ bfc,
                                                      const int* __restrict__ tgt_raw,
                                                      float* __restrict__ out,
                                                      long long loss_idx,
                                                      int n_logit_blocks) {
    int b = blockIdx.x;
    int tid = threadIdx.x;

    if (b > 0 && b <= n_logit_blocks) {
        // ------------- logits -------------
        int bb2 = b - 1;
        __shared__ float sh0[8], sh1[8];
        int tb = (bb2 & 511) * 8;
        if (tid < 8) {
            sh0[tid] = g_h0[tb + tid];
            sh1[tid] = g_h1[tb + tid];
        }
        __syncthreads();
        float h0r[8], h1r[8];
#pragma unroll
        for (int r = 0; r < 8; r++) { h0r[r] = sh0[r]; h1r[r] = sh1[r]; }

        const int vbeg = (bb2 >> 9) * 4000;
        const int vend = vbeg + 4000;
        for (int v = vbeg + tid * 4; v < vend; v += 1024) {
            float4 wa = *(const float4*)(Wfc + 2 * v);      // w0,w1 of v, v+1
            float4 wb = *(const float4*)(Wfc + 2 * v + 4);  // w0,w1 of v+2, v+3
            float4 bb = *(const float4*)(bfc + v);
            float* op = out + (size_t)tb * VV + v;
#pragma unroll
            for (int r = 0; r < 8; r++) {
                float4 o;
                o.x = fmaf(h0r[r], wa.x, fmaf(h1r[r], wa.y, bb.x));
                o.y = fmaf(h0r[r], wa.z, fmaf(h1r[r], wa.w, bb.y));
                o.z = fmaf(h0r[r], wb.x, fmaf(h1r[r], wb.y, bb.z));
                o.w = fmaf(h0r[r], wb.z, fmaf(h1r[r], wb.w, bb.w));
                __stcs((float4*)(op + (size_t)r * VV), o);
            }
        }
    } else if (b == 0) {
        // ------------- loss (wave-1 block, hides under logits stores) ---------
        __shared__ float sC[121];
        if (tid < 121)
            sC[tid] = g_Cm[tid] + g_Cm[121 + tid] + g_Cm[242 + tid] + g_Cm[363 + tid];

        // detect int64 vs int32 targets: int64 (LE) => all odd 32-bit words of
        // the first 4096 words are zero (values < 32000). OOB-safe either way.
        int local = 0;
        for (int i = tid; i < TT / 2; i += 256) local |= tgt_raw[2 * i + 1];
        int nz = __syncthreads_or(local);
        int is64 = (nz == 0);

        float acc = 0.f;
#pragma unroll
        for (int r = 0; r < 16; r++) {
            int t = r * 256 + tid;
            float h0 = g_h0[t];
            float h1 = g_h1[t];
            // sumexp(h) = sum_{j,k<=10} C_jk h0^j h1^k (double Horner)
            float S = 0.f;
#pragma unroll
            for (int j = 10; j >= 0; j--) {
                const float* row = &sC[j * 11];
                float inner = row[10];
#pragma unroll
                for (int k = 9; k >= 0; k--) inner = fmaf(inner, h1, row[k]);
                S = fmaf(S, h0, inner);
            }
            int g = is64 ? tgt_raw[2 * t] : tgt_raw[t];
            float lt = fmaf(h0, Wfc[2 * g], fmaf(h1, Wfc[2 * g + 1], bfc[g]));
            acc += logf(S) - lt;
        }

#pragma unroll
        for (int o = 16; o; o >>= 1) acc += __shfl_down_sync(0xffffffffu, acc, o);
        __shared__ float s[8];
        if ((tid & 31) == 0) s[tid >> 5] = acc;
        __syncthreads();
        if (tid == 0) {
            float tot = 0.f;
#pragma unroll
            for (int w = 0; w < 8; w++) tot += s[w];
            if (loss_idx >= 0) out[loss_idx] = tot * (1.0f / TT);
        }
    }
}

// ---------------- launch ----------------
extern "C" void kernel_launch(void* const* d_in, const int* in_sizes, int n_in,
                              void* d_out, int out_size) {
    const float* x       = (const float*)d_in[0];
    const int*   targets = (const int*)d_in[1];   // int32 or int64, detected on device
    const float* Wih     = (const float*)d_in[2];
    const float* bih     = (const float*)d_in[3];
    const float* Whh     = (const float*)d_in[4];
    const float* bhh     = (const float*)d_in[5];
    const float* Wfc     = (const float*)d_in[6];
    const float* bfc     = (const float*)d_in[7];
    float* out = (float*)d_out;

    const long long logits_elems = (long long)TT * VV;

    k1_pre_moments<<<PRE_BLOCKS + MOM_BLOCKS, 256>>>(x, Wih, Wfc, bfc);
    k2_scan<<<1, 1024>>>(Whh, bih, bhh);

    int n_logit_blocks = ((long long)out_size >= logits_elems) ? 4096 : 0;
    long long loss_idx = -1;
    if ((long long)out_size > logits_elems) loss_idx = logits_elems;  // logits + loss
    else if (out_size == 1) loss_idx = 0;                             // loss only
    k3_logits_loss<<<n_logit_blocks + 1, 256>>>(Wfc, bfc, targets, out,
                                                loss_idx, n_logit_blocks);
}

// round 14
// speedup vs baseline: 2.1383x; 1.0037x over previous
#include <cuda_runtime.h>
#include <math.h>

#define TT 4096
#define DD 4096
#define VV 32000
#define NCHUNK 4                       // D split into 4 chunks of 1024 floats
#define ROWS_PB 16                     // rows per pre-block
#define PRE_BLOCKS ((TT / ROWS_PB) * 4)        // 1024
#define MOM_BLOCKS (11 * 4)            // j x v-chunk

// ---------------- scratch (device globals; no allocations) ----------------
__device__ float g_part[NCHUNK * TT * 2];   // partial pre sums, [chunk][t][h]
__device__ float g_h0[TT];
__device__ float g_h1[TT];
__device__ float g_Cm[4 * 121];             // moment partials per v-chunk

__device__ __constant__ float c_invfact[11] = {
    1.0f, 1.0f, 0.5f, 1.6666667e-1f, 4.1666668e-2f, 8.3333338e-3f,
    1.3888889e-3f, 1.9841270e-4f, 2.4801588e-5f, 2.7557319e-6f, 2.7557319e-7f
};

// accurate-enough tanh: exact +-1 in saturation (matches fp32 tanh rounding),
// ~1e-7 error elsewhere (EX2 + RCP)
__device__ __forceinline__ float tanh_acc(float a) {
    float ab = fabsf(a);
    if (ab > 9.1f) return copysignf(1.0f, a);
    float e = __expf(-2.0f * ab);
    float r = __fdividef(1.0f - e, 1.0f + e);
    return copysignf(r, a);
}

// ---------------- K1: pre-GEMV partials (16 rows/thread-col, butterfly red) --
__global__ __launch_bounds__(256, 2) void k1_pre_moments(const float* __restrict__ x,
                                                         const float* __restrict__ Wih,
                                                         const float* __restrict__ Wfc,
                                                         const float* __restrict__ bfc) {
    int b = blockIdx.x;
    int tid = threadIdx.x;

    if (b < PRE_BLOCKS) {
        int rt = b >> 2;                 // row tile (0..255)
        int c  = b & 3;                  // D-chunk (0..3)
        int t0 = rt * ROWS_PB;
        int i  = c * 256 + tid;          // float4 column index within row

        const float4* w0g = (const float4*)(Wih);
        const float4* w1g = (const float4*)(Wih + DD);
        float4 w0 = __ldg(&w0g[i]);
        float4 w1 = __ldg(&w1g[i]);

        // 16 independent streaming loads, front-batched for MLP
        float4 xv[ROWS_PB];
        const float4* xb = (const float4*)(x) + (size_t)t0 * (DD / 4) + i;
#pragma unroll
        for (int r = 0; r < ROWS_PB; r++) xv[r] = __ldcs(xb + (size_t)r * (DD / 4));

        float a[32];
#pragma unroll
        for (int r = 0; r < ROWS_PB; r++) {
            float4 v = xv[r];
            a[2 * r]     = fmaf(v.x, w0.x, fmaf(v.y, w0.y, fmaf(v.z, w0.z, v.w * w0.w)));
            a[2 * r + 1] = fmaf(v.x, w1.x, fmaf(v.y, w1.y, fmaf(v.z, w1.z, v.w * w1.w)));
        }

        // butterfly multi-value reduce: 31 shfls; lane l ends holding slot l
        int lane = tid & 31;
#pragma unroll
        for (int o = 16; o; o >>= 1) {
#pragma unroll
            for (int j = 0; j < o; j++) {
                bool hi = (lane & o);
                float pass = hi ? a[j] : a[j + o];
                float recv = __shfl_xor_sync(0xffffffffu, pass, o);
                a[j] = (hi ? a[j + o] : a[j]) + recv;
            }
        }

        __shared__ float sred[8][33];
        int wid = tid >> 5;
        sred[wid][lane] = a[0];
        __syncthreads();
        if (tid < 32) {
            float s = 0.f;
#pragma unroll
            for (int w = 0; w < 8; w++) s += sred[w][tid];
            g_part[((size_t)c * TT + t0) * 2 + tid] = s;
        }
    } else {
        // ---- moments partials: block (j, vc), each covers V/4 elements ----
        int m = b - PRE_BLOCKS;
        int j  = m >> 2;
        int vc = m & 3;
        float acc[11];
#pragma unroll
        for (int k = 0; k < 11; k++) acc[k] = 0.f;

        int vbeg = vc * (VV / 4), vend = vbeg + (VV / 4);
        for (int v = vbeg + tid; v < vend; v += 256) {
            float2 w = *(const float2*)(Wfc + 2 * v);
            float p = __expf(bfc[v]);
#pragma unroll
            for (int a2 = 0; a2 < 10; a2++) {
                if (a2 < j) p *= w.x;
            }
#pragma unroll
            for (int k = 0; k < 11; k++) {
                acc[k] += p;
                p *= w.y;
            }
        }
        __shared__ float sredm[8][11];
#pragma unroll
        for (int k = 0; k < 11; k++) {
#pragma unroll
            for (int o = 16; o; o >>= 1)
                acc[k] += __shfl_down_sync(0xffffffffu, acc[k], o);
        }
        if ((tid & 31) == 0) {
#pragma unroll
            for (int k = 0; k < 11; k++) sredm[tid >> 5][k] = acc[k];
        }
        __syncthreads();
        if (tid < 11) {
            float tot = 0.f;
#pragma unroll
            for (int w = 0; w < 8; w++) tot += sredm[w][tid];
            g_Cm[vc * 121 + j * 11 + tid] = tot * c_invfact[j] * c_invfact[tid];
        }
    }
}

// ---------------- K2: sum partials + biases (front-batched), segmented scan --
__global__ __launch_bounds__(1024) void k2_scan(const float* __restrict__ Whh,
                                                const float* __restrict__ bih,
                                                const float* __restrict__ bhh) {
    __shared__ float sp0[TT];
    __shared__ float sp1[TT];
    int tid = threadIdx.x;
    float c0 = bih[0] + bhh[0];
    float c1 = bih[1] + bhh[1];
    for (int t = tid; t < TT; t += 1024) {
        float2 v[NCHUNK];
#pragma unroll
        for (int c = 0; c < NCHUNK; c++)
            v[c] = *(const float2*)&g_part[((size_t)c * TT + t) * 2];
        float p0 = c0, p1 = c1;
#pragma unroll
        for (int c = 0; c < NCHUNK; c++) { p0 += v[c].x; p1 += v[c].y; }
        sp0[t] = p0;
        sp1[t] = p1;
    }
    __syncthreads();

    float W00 = Whh[0], W01 = Whh[1], W10 = Whh[2], W11 = Whh[3];
    float th0 = 9.2f + fabsf(W00) + fabsf(W01);
    float th1 = 9.2f + fabsf(W10) + fabsf(W11);

#pragma unroll
    for (int k = 0; k < 5; k++) {
        int idx = tid + k * 1024;
        if (k == 4 && tid != 0) break;
        if (k == 4) idx = TT;

        float h0, h1;
        int t;
        if (idx == 0) {
            h0 = 0.f; h1 = 0.f; t = 0;
        } else {
            int r = idx - 1;
            float p0 = sp0[r], p1 = sp1[r];
            if (!(fabsf(p0) > th0 && fabsf(p1) > th1)) continue;
            h0 = copysignf(1.0f, p0);   // saturated: tanh == +-1.0f exactly
            h1 = copysignf(1.0f, p1);
            g_h0[r] = h0;
            g_h1[r] = h1;
            t = r + 1;
        }
        while (t < TT) {
            float p0 = sp0[t], p1 = sp1[t];
            if (fabsf(p0) > th0 && fabsf(p1) > th1) break;
            float a0 = fmaf(W01, h1, fmaf(W00, h0, p0));
            float a1 = fmaf(W11, h1, fmaf(W10, h0, p1));
            h0 = tanh_acc(a0);
            h1 = tanh_acc(a1);
            g_h0[t] = h0;
            g_h1[t] = h1;
            t++;
        }
    }
}

// ---------------- K3: logits (HBM-write bound, 4-row tiles for occupancy) ----
// loss block = blockIdx 0; logits blocks = 1..n_logit_blocks
// logits block bb2: t-tile = (bb2 & 1023)*4, v-chunk = (bb2 >> 10)*4000
__global__ __launch_bounds__(256) void k3_logits_loss(const float* __restrict__ Wfc,
                                                      const float* __restrict__ bfc,
                                                      const int* __restrict__ tgt_raw,
                                                      float* __restrict__ out,
                                                      long long loss_idx,
                                                      int n_logit_blocks) {
    int b = blockIdx.x;
    int tid = threadIdx.x;

    if (b > 0 && b <= n_logit_blocks) {
        // ------------- logits -------------
        int bb2 = b - 1;
        __shared__ float sh0[4], sh1[4];
        int tb = (bb2 & 1023) * 4;
        if (tid < 4) {
            sh0[tid] = g_h0[tb + tid];
            sh1[tid] = g_h1[tb + tid];
        }
        __syncthreads();
        float h0r[4], h1r[4];
#pragma unroll
        for (int r = 0; r < 4; r++) { h0r[r] = sh0[r]; h1r[r] = sh1[r]; }

        const int vbeg = (bb2 >> 10) * 4000;
        const int vend = vbeg + 4000;
        for (int v = vbeg + tid * 4; v < vend; v += 1024) {
            float4 wa = *(const float4*)(Wfc + 2 * v);      // w0,w1 of v, v+1
            float4 wb = *(const float4*)(Wfc + 2 * v + 4);  // w0,w1 of v+2, v+3
            float4 bb = *(const float4*)(bfc + v);
            float* op = out + (size_t)tb * VV + v;
#pragma unroll
            for (int r = 0; r < 4; r++) {
                float4 o;
                o.x = fmaf(h0r[r], wa.x, fmaf(h1r[r], wa.y, bb.x));
                o.y = fmaf(h0r[r], wa.z, fmaf(h1r[r], wa.w, bb.y));
                o.z = fmaf(h0r[r], wb.x, fmaf(h1r[r], wb.y, bb.z));
                o.w = fmaf(h0r[r], wb.z, fmaf(h1r[r], wb.w, bb.w));
                __stcs((float4*)(op + (size_t)r * VV), o);
            }
        }
    } else if (b == 0) {
        // ------------- loss (wave-1 block, hides under logits stores) ---------
        __shared__ float sC[121];
        if (tid < 121)
            sC[tid] = g_Cm[tid] + g_Cm[121 + tid] + g_Cm[242 + tid] + g_Cm[363 + tid];

        // detect int64 vs int32 targets: int64 (LE) => all odd 32-bit words of
        // the first 4096 words are zero (values < 32000). OOB-safe either way.
        int local = 0;
        for (int i = tid; i < TT / 2; i += 256) local |= tgt_raw[2 * i + 1];
        int nz = __syncthreads_or(local);
        int is64 = (nz == 0);

        float acc = 0.f;
#pragma unroll
        for (int r = 0; r < 16; r++) {
            int t = r * 256 + tid;
            float h0 = g_h0[t];
            float h1 = g_h1[t];
            // sumexp(h) = sum_{j,k<=10} C_jk h0^j h1^k (double Horner)
            float S = 0.f;
#pragma unroll
            for (int j = 10; j >= 0; j--) {
                const float* row = &sC[j * 11];
                float inner = row[10];
#pragma unroll
                for (int k = 9; k >= 0; k--) inner = fmaf(inner, h1, row[k]);
                S = fmaf(S, h0, inner);
            }
            int g = is64 ? tgt_raw[2 * t] : tgt_raw[t];
            float lt = fmaf(h0, Wfc[2 * g], fmaf(h1, Wfc[2 * g + 1], bfc[g]));
            acc += logf(S) - lt;
        }

#pragma unroll
        for (int o = 16; o; o >>= 1) acc += __shfl_down_sync(0xffffffffu, acc, o);
        __shared__ float s[8];
        if ((tid & 31) == 0) s[tid >> 5] = acc;
        __syncthreads();
        if (tid == 0) {
            float tot = 0.f;
#pragma unroll
            for (int w = 0; w < 8; w++) tot += s[w];
            if (loss_idx >= 0) out[loss_idx] = tot * (1.0f / TT);
        }
    }
}

// ---------------- launch ----------------
extern "C" void kernel_launch(void* const* d_in, const int* in_sizes, int n_in,
                              void* d_out, int out_size) {
    const float* x       = (const float*)d_in[0];
    const int*   targets = (const int*)d_in[1];   // int32 or int64, detected on device
    const float* Wih     = (const float*)d_in[2];
    const float* bih     = (const float*)d_in[3];
    const float* Whh     = (const float*)d_in[4];
    const float* bhh     = (const float*)d_in[5];
    const float* Wfc     = (const float*)d_in[6];
    const float* bfc     = (const float*)d_in[7];
    float* out = (float*)d_out;

    const long long logits_elems = (long long)TT * VV;

    k1_pre_moments<<<PRE_BLOCKS + MOM_BLOCKS, 256>>>(x, Wih, Wfc, bfc);
    k2_scan<<<1, 1024>>>(Whh, bih, bhh);

    int n_logit_blocks = ((long long)out_size >= logits_elems) ? 8192 : 0;
    long long loss_idx = -1;
    if ((long long)out_size > logits_elems) loss_idx = logits_elems;  // logits + loss
    else if (out_size == 1) loss_idx = 0;                             // loss only
    k3_logits_loss<<<n_logit_blocks + 1, 256>>>(Wfc, bfc, targets, out,
                                                loss_idx, n_logit_blocks);
}